// round 10
// baseline (speedup 1.0000x reference)
#include <cuda_runtime.h>
#include <cuda_bf16.h>
#include <cstdint>

#define NG   2048
#define MAXN 500000
#define BN_EPS 1e-5f

typedef unsigned long long ull;

// ---------------- scratch (device globals; no allocation allowed) ----------------
__device__ __align__(16) __nv_bfloat16 g_hhi[(size_t)MAXN * 128];
__device__ __align__(16) __nv_bfloat16 g_hlo[(size_t)MAXN * 128];
__device__ __align__(16) float g_y[(size_t)MAXN * 128];
__device__ __align__(16) float g_lam1[NG * 128];
__device__ __align__(16) float g_lam2[NG * 128];
__device__ __align__(16) float g_psum[NG * 128];
__device__ __align__(16) float g_psq[NG * 128];
__device__ __align__(16) float g_scale[128];
__device__ __align__(16) float g_shift[128];
__device__ int g_seg[NG + 1];

// ---------------- helpers ----------------
__device__ __forceinline__ uint32_t smaddr(const void* p) {
    return (uint32_t)__cvta_generic_to_shared(p);
}
__device__ __forceinline__ void cp16(uint32_t d, const void* s, int n) {
    asm volatile("cp.async.ca.shared.global [%0], [%1], 16, %2;\n" :: "r"(d), "l"(s), "r"(n));
}
#define CP_COMMIT() asm volatile("cp.async.commit_group;\n" ::: "memory")
#define CP_WAIT0()  asm volatile("cp.async.wait_group 0;\n" ::: "memory")

// bf16x2 mma (m16n8k16, sm_80+, compiles for plain sm_103)
__device__ __forceinline__ void mma_bf16(float* d, const uint32_t* a, const uint32_t* b) {
    asm volatile(
        "mma.sync.aligned.m16n8k16.row.col.f32.bf16.bf16.f32 "
        "{%0,%1,%2,%3}, {%4,%5,%6,%7}, {%8,%9}, {%0,%1,%2,%3};"
        : "+f"(d[0]), "+f"(d[1]), "+f"(d[2]), "+f"(d[3])
        : "r"(a[0]), "r"(a[1]), "r"(a[2]), "r"(a[3]), "r"(b[0]), "r"(b[1]));
}
__device__ __forceinline__ void ldsm4(uint32_t* r, uint32_t a) {
    asm volatile("ldmatrix.sync.aligned.m8n8.x4.shared.b16 {%0,%1,%2,%3}, [%4];"
        : "=r"(r[0]), "=r"(r[1]), "=r"(r[2]), "=r"(r[3]) : "r"(a));
}

// split fp32 pair -> packed bf16 hi / lo residual
__device__ __forceinline__ void bsplit2(float a, float b, uint32_t& hi, uint32_t& lo) {
    __nv_bfloat162 h = __floats2bfloat162_rn(a, b);
    hi = *reinterpret_cast<uint32_t*>(&h);
    float ra = a - __bfloat162float(h.x);
    float rb = b - __bfloat162float(h.y);
    __nv_bfloat162 l = __floats2bfloat162_rn(ra, rb);
    lo = *reinterpret_cast<uint32_t*>(&l);
}

// ---- gemm1 smem map (64-row tiles, ROWB=304, K=144) ----
#define ROWB 304
#define OFF_BH 512
#define OFF_BL (OFF_BH + 38912)
#define OFF_A  (OFF_BL + 38912)
#define OFF_EPI (OFF_A + 77824)
#define SMEM_G1 (OFF_EPI + 16896)     // 173056 B

// ---- gemm2 smem map (128-row tiles, ROWB2=272, K=128) ----
#define ROWB2 272
#define O2_BH 512
#define O2_BL (O2_BH + 34816)
#define O2_A  (O2_BL + 34816)          // 2 bufs x 69632 (hi 34816 + lo 34816)
#define O2_EPI (O2_A + 139264)         // 209408
#define SMEM_G2 (O2_EPI + 16896)       // 226304 B

// ---------------- K0: segment bounds (batch sorted) ----------------
__global__ void k_bounds(const int* __restrict__ batch, int N) {
    int g = blockIdx.x * blockDim.x + threadIdx.x;
    if (g > NG) return;
    int lo = 0, hi = N;
    while (lo < hi) {
        int mid = (lo + hi) >> 1;
        if (batch[mid] < g) lo = mid + 1; else hi = mid;
    }
    g_seg[g] = lo;
}

// ---------------- K1: per-graph col means of x0 + lam1 = xm @ l1w^T ----------------
__global__ void k_lam1(const float* __restrict__ x, const float* __restrict__ pers0,
                       const float* __restrict__ l1w, int N) {
    __shared__ float s_sum[2][144];
    __shared__ float s_xm[144];
    int g  = blockIdx.x;
    int lo = g_seg[g], hi = g_seg[g + 1];
    int t  = threadIdx.x;
    int phase = t / 144, col = t - phase * 144;

    float acc = 0.f;
    if (col < 128) {
        const float* p = x + col;
        for (int r = lo + phase; r < hi; r += 2) acc += p[(size_t)r * 128];
    } else {
        int j = col - 128;
        int pp = j >> 1, c = j & 1;
        const float* p = pers0 + (size_t)pp * 2 * N + c;
        for (int r = lo + phase; r < hi; r += 2) acc += p[2 * (size_t)r];
    }
    s_sum[phase][col] = acc;
    __syncthreads();
    if (t < 144) {
        float cnt = (float)max(hi - lo, 1);
        s_xm[t] = (s_sum[0][t] + s_sum[1][t]) / cnt;
    }
    __syncthreads();
    if (t < 128) {
        const float* w = l1w + t * 144;
        float a = 0.f;
#pragma unroll 8
        for (int k = 0; k < 144; ++k) a += s_xm[k] * w[k];
        g_lam1[g * 128 + t] = a;
    }
}

// =============== K2: mma.sync GEMM1: h = relu(x0 @ g1w^T + g1b - lam1[g]) ===============
// 64-row tiles, 8 warps as 2M x 4N (warp: 32 rows x 32 cols). K=144 = 9 k16 steps.
__global__ __launch_bounds__(256, 1) void k_gemm1(
    const float* __restrict__ x, const float* __restrict__ pers0,
    const float* __restrict__ g1w, const float* __restrict__ g1b,
    const float* __restrict__ l2w, int N) {
    extern __shared__ char sm[];
    uint32_t su = smaddr(sm);
    float* sbias = (float*)sm;
    int g  = blockIdx.x;
    int lo = g_seg[g], hi = g_seg[g + 1];
    int tid = threadIdx.x;
    int wid = tid >> 5, l = tid & 31;
    int wm = wid & 1, wn = wid >> 1;           // 2M x 4N
    int seg = l >> 3, l7 = l & 7, gg = l >> 2, tg = l & 3;

    // stage B = g1w as bf16 hi/lo, row stride 304B
    for (int it = 0; it < 18; ++it) {
        int idx = tid + it * 256;            // [0, 128*36)
        int jr = idx / 36, k4 = idx - jr * 36;
        float4 v = ((const float4*)g1w)[idx];
        uint32_t h01, l01, h23, l23;
        bsplit2(v.x, v.y, h01, l01);
        bsplit2(v.z, v.w, h23, l23);
        int off = jr * ROWB + k4 * 8;
        *(uint2*)(sm + OFF_BH + off) = make_uint2(h01, h23);
        *(uint2*)(sm + OFF_BL + off) = make_uint2(l01, l23);
    }
    if (tid < 128) sbias[tid] = g1b[tid] - g_lam1[g * 128 + tid];

    // register prefetch of one 64-row x0 tile (row = tid>>2, k-quarter = tid&3)
    float4 xv[8]; float2 pv[2];
    int prow = tid >> 2, pkq = tid & 3;
    auto loadRegs = [&](int r0i, int rem) {
        int rg = r0i + min(prow, rem - 1);
        const float4* xs = (const float4*)(x + (size_t)rg * 128) + pkq * 8;
#pragma unroll
        for (int i = 0; i < 8; ++i) xv[i] = xs[i];
        int p0 = pkq * 2;
        pv[0] = *(const float2*)(pers0 + (size_t)p0 * 2 * N + 2 * (size_t)rg);
        pv[1] = *(const float2*)(pers0 + (size_t)(p0 + 1) * 2 * N + 2 * (size_t)rg);
    };
    auto stsRegs = [&](int buf) {
        char* bh = sm + OFF_A + buf * 38912 + prow * ROWB;
        char* bl = bh + 19456;
#pragma unroll
        for (int i = 0; i < 8; ++i) {
            uint32_t h01, l01, h23, l23;
            bsplit2(xv[i].x, xv[i].y, h01, l01);
            bsplit2(xv[i].z, xv[i].w, h23, l23);
            *(uint2*)(bh + pkq * 64 + i * 8) = make_uint2(h01, h23);
            *(uint2*)(bl + pkq * 64 + i * 8) = make_uint2(l01, l23);
        }
        uint32_t h01, l01, h23, l23;
        bsplit2(pv[0].x, pv[0].y, h01, l01);
        bsplit2(pv[1].x, pv[1].y, h23, l23);
        *(uint2*)(bh + 256 + pkq * 8) = make_uint2(h01, h23);
        *(uint2*)(bl + 256 + pkq * 8) = make_uint2(l01, l23);
    };

    float hs[16];
#pragma unroll
    for (int i = 0; i < 16; ++i) hs[i] = 0.f;

    uint32_t a_off = su + OFF_A  + (uint32_t)((wm * 32 + (seg & 1) * 8 + l7) * ROWB + (seg >> 1) * 16);
    uint32_t b_off = su + OFF_BH + (uint32_t)((wn * 32 + (seg >> 1) * 8 + l7) * ROWB + (seg & 1) * 16);

    if (lo < hi) { loadRegs(lo, min(64, hi - lo)); stsRegs(0); }
    __syncthreads();

    int t = 0;
    for (int r0 = lo; r0 < hi; r0 += 64, ++t) {
        int buf = t & 1;
        int nr0 = r0 + 64;
        bool havnext = nr0 < hi;
        if (havnext) loadRegs(nr0, min(64, hi - nr0));

        float D[8][4];
#pragma unroll
        for (int i = 0; i < 8; ++i)
#pragma unroll
            for (int q = 0; q < 4; ++q) D[i][q] = 0.f;

        uint32_t abase = a_off + buf * 38912;
#pragma unroll
        for (int ks = 0; ks < 9; ++ks) {
            uint32_t ah[2][4], al[2][4];
            ldsm4(ah[0], abase + ks * 32);
            ldsm4(al[0], abase + 19456 + ks * 32);
            ldsm4(ah[1], abase + 16 * ROWB + ks * 32);
            ldsm4(al[1], abase + 16 * ROWB + 19456 + ks * 32);
#pragma unroll
            for (int nt = 0; nt < 2; ++nt) {
                uint32_t bb = b_off + nt * (16 * ROWB) + ks * 32;
                uint32_t bhf[4], blf[4];
                ldsm4(bhf, bb);
                ldsm4(blf, bb + 38912);
#pragma unroll
                for (int m = 0; m < 2; ++m) {
                    float* d0 = D[m * 4 + nt * 2];
                    float* d1 = D[m * 4 + nt * 2 + 1];
                    mma_bf16(d0, ah[m], bhf);
                    mma_bf16(d1, ah[m], bhf + 2);
                    mma_bf16(d0, ah[m], blf);
                    mma_bf16(d1, ah[m], blf + 2);
                    mma_bf16(d0, al[m], bhf);
                    mma_bf16(d1, al[m], bhf + 2);
                }
            }
        }
        if (havnext) stsRegs(buf ^ 1);

        // epilogue: 2 phases of 32 rows
        float* epi = (float*)(sm + OFF_EPI);
#pragma unroll
        for (int p = 0; p < 2; ++p) {
            __syncthreads();
            if (wm == p) {
#pragma unroll
                for (int m = 0; m < 2; ++m)
#pragma unroll
                for (int nt = 0; nt < 2; ++nt)
#pragma unroll
                for (int h = 0; h < 2; ++h) {
                    int d = m * 4 + nt * 2 + h;
                    int er = m * 16 + gg;
                    int c = wn * 32 + nt * 16 + h * 8 + 2 * tg;
                    *(float2*)(epi + er * 132 + c)       = make_float2(D[d][0], D[d][1]);
                    *(float2*)(epi + (er + 8) * 132 + c) = make_float2(D[d][2], D[d][3]);
                }
            }
            __syncthreads();
            int r = tid >> 3, c0 = (tid & 7) * 16;
            int grow = r0 + p * 32 + r;
            if (grow < hi) {
                float v[16];
#pragma unroll
                for (int q = 0; q < 4; ++q)
                    *(float4*)(v + 4 * q) = *(const float4*)(epi + r * 132 + c0 + 4 * q);
                uint32_t hh[8], ll[8];
#pragma unroll
                for (int i = 0; i < 16; i += 2) {
                    float va = fmaxf(v[i]     + sbias[c0 + i],     0.f);
                    float vb = fmaxf(v[i + 1] + sbias[c0 + i + 1], 0.f);
                    hs[i] += va; hs[i + 1] += vb;
                    bsplit2(va, vb, hh[i >> 1], ll[i >> 1]);
                }
                size_t off = (size_t)grow * 128 + c0;
                *(uint4*)(g_hhi + off)     = make_uint4(hh[0], hh[1], hh[2], hh[3]);
                *(uint4*)(g_hhi + off + 8) = make_uint4(hh[4], hh[5], hh[6], hh[7]);
                *(uint4*)(g_hlo + off)     = make_uint4(ll[0], ll[1], ll[2], ll[3]);
                *(uint4*)(g_hlo + off + 8) = make_uint4(ll[4], ll[5], ll[6], ll[7]);
            }
        }
        __syncthreads();
    }

    // deterministic col-sum reduce -> hm -> lam2 = hm @ l2w^T
    float* red = (float*)(sm + OFF_EPI);
    __syncthreads();
#pragma unroll
    for (int i = 0; i < 16; ++i) red[tid * 16 + i] = hs[i];
    __syncthreads();
    if (tid < 128) {
        int o = tid >> 4, i = tid & 15;
        float s = 0.f;
        for (int ss = 0; ss < 32; ++ss) s += red[(ss * 8 + o) * 16 + i];
        float cnt = (float)max(hi - lo, 1);
        red[4096 + o * 16 + i] = s / cnt;
    }
    __syncthreads();
    if (tid < 128) {
        const float* w = l2w + tid * 128;
        const float* hm = red + 4096;
        float a = 0.f;
#pragma unroll 8
        for (int k = 0; k < 128; ++k) a += hm[k] * w[k];
        g_lam2[g * 128 + tid] = a;
    }
}

// =============== K4: mma.sync GEMM2: y0 = h @ g2w^T + g2b - lam2[g]; BN partials ===============
// 128-row tiles, 8 warps as 2M x 4N (warp: 64 rows x 32 cols). K=128 = 8 k16 steps.
__global__ __launch_bounds__(256, 1) void k_gemm2(
    const float* __restrict__ g2w, const float* __restrict__ g2b, int N) {
    extern __shared__ char sm[];
    uint32_t su = smaddr(sm);
    float* sbias = (float*)sm;
    int g  = blockIdx.x;
    int lo = g_seg[g], hi = g_seg[g + 1];
    int tid = threadIdx.x;
    int wid = tid >> 5, l = tid & 31;
    int wm = wid & 1, wn = wid >> 1;
    int seg = l >> 3, l7 = l & 7, gg = l >> 2, tg = l & 3;

    // stage B = g2w bf16 hi/lo (K=128), row stride 272B
    for (int it = 0; it < 16; ++it) {
        int idx = tid + it * 256;            // [0, 128*32)
        int jr = idx >> 5, k4 = idx & 31;
        float4 v = ((const float4*)g2w)[idx];
        uint32_t h01, l01, h23, l23;
        bsplit2(v.x, v.y, h01, l01);
        bsplit2(v.z, v.w, h23, l23);
        int off = jr * ROWB2 + k4 * 8;
        *(uint2*)(sm + O2_BH + off) = make_uint2(h01, h23);
        *(uint2*)(sm + O2_BL + off) = make_uint2(l01, l23);
    }
    if (tid < 128) sbias[tid] = g2b[tid] - g_lam2[g * 128 + tid];

    // A staging via cp.async from pre-split h arrays (128 rows per tile)
    auto stageA = [&](int r0i, int rem, int buf) {
#pragma unroll
        for (int hl = 0; hl < 2; ++hl) {
            const __nv_bfloat16* src = hl ? g_hlo : g_hhi;
            uint32_t base = su + O2_A + buf * 69632 + hl * 34816;
#pragma unroll
            for (int it = 0; it < 8; ++it) {
                int idx = tid + it * 256;        // [0, 128*16)
                int r = idx >> 4, u = idx & 15;
                int rc = (r < rem) ? r : 0;
                cp16(base + r * ROWB2 + u * 16,
                     src + (size_t)(r0i + rc) * 128 + u * 8, (r < rem) ? 16 : 0);
            }
        }
    };

    float ssum[16], ssq[16];
#pragma unroll
    for (int i = 0; i < 16; ++i) { ssum[i] = 0.f; ssq[i] = 0.f; }

    uint32_t a_off = su + O2_A  + (uint32_t)((wm * 64 + (seg & 1) * 8 + l7) * ROWB2 + (seg >> 1) * 16);
    uint32_t b_off = su + O2_BH + (uint32_t)((wn * 32 + (seg >> 1) * 8 + l7) * ROWB2 + (seg & 1) * 16);

    if (lo < hi) { stageA(lo, min(128, hi - lo), 0); CP_COMMIT(); CP_WAIT0(); }
    __syncthreads();

    int t = 0;
    for (int r0 = lo; r0 < hi; r0 += 128, ++t) {
        int buf = t & 1;
        int nr0 = r0 + 128;
        bool havnext = nr0 < hi;
        if (havnext) { stageA(nr0, min(128, hi - nr0), buf ^ 1); CP_COMMIT(); }

        float D[16][4];
#pragma unroll
        for (int i = 0; i < 16; ++i)
#pragma unroll
            for (int q = 0; q < 4; ++q) D[i][q] = 0.f;

        uint32_t abase = a_off + buf * 69632;
#pragma unroll
        for (int ks = 0; ks < 8; ++ks) {
            uint32_t ah[4][4], al[4][4];
#pragma unroll
            for (int m = 0; m < 4; ++m) {
                ldsm4(ah[m], abase + m * (16 * ROWB2) + ks * 32);
                ldsm4(al[m], abase + m * (16 * ROWB2) + 34816 + ks * 32);
            }
#pragma unroll
            for (int nt = 0; nt < 2; ++nt) {
                uint32_t bb = b_off + nt * (16 * ROWB2) + ks * 32;
                uint32_t bhf[4], blf[4];
                ldsm4(bhf, bb);
                ldsm4(blf, bb + 34816);
#pragma unroll
                for (int m = 0; m < 4; ++m) {
                    float* d0 = D[m * 4 + nt * 2];
                    float* d1 = D[m * 4 + nt * 2 + 1];
                    mma_bf16(d0, ah[m], bhf);
                    mma_bf16(d1, ah[m], bhf + 2);
                    mma_bf16(d0, ah[m], blf);
                    mma_bf16(d1, ah[m], blf + 2);
                    mma_bf16(d0, al[m], bhf);
                    mma_bf16(d1, al[m], bhf + 2);
                }
            }
        }

        // epilogue: 4 phases of 32 rows
        float* epi = (float*)(sm + O2_EPI);
#pragma unroll
        for (int p = 0; p < 4; ++p) {
            __syncthreads();
            if (wm == (p >> 1)) {
                int mb = (p & 1) * 2;
#pragma unroll
                for (int mi = 0; mi < 2; ++mi)
#pragma unroll
                for (int nt = 0; nt < 2; ++nt)
#pragma unroll
                for (int h = 0; h < 2; ++h) {
                    int d = (mb + mi) * 4 + nt * 2 + h;
                    int er = mi * 16 + gg;
                    int c = wn * 32 + nt * 16 + h * 8 + 2 * tg;
                    *(float2*)(epi + er * 132 + c)       = make_float2(D[d][0], D[d][1]);
                    *(float2*)(epi + (er + 8) * 132 + c) = make_float2(D[d][2], D[d][3]);
                }
            }
            __syncthreads();
            int r = tid >> 3, c0 = (tid & 7) * 16;
            int grow = r0 + p * 32 + r;
            if (grow < hi) {
                float v[16];
#pragma unroll
                for (int q = 0; q < 4; ++q)
                    *(float4*)(v + 4 * q) = *(const float4*)(epi + r * 132 + c0 + 4 * q);
#pragma unroll
                for (int i = 0; i < 16; ++i) {
                    float vv = v[i] + sbias[c0 + i];
                    v[i] = vv;
                    ssum[i] += vv;
                    ssq[i]  += vv * vv;
                }
                float* dst = g_y + (size_t)grow * 128 + c0;
#pragma unroll
                for (int q = 0; q < 4; ++q) *(float4*)(dst + 4 * q) = *(float4*)(v + 4 * q);
            }
        }
        if (havnext) CP_WAIT0();
        __syncthreads();
    }

    // deterministic BN partials
    float* red = (float*)(sm + O2_EPI);
    __syncthreads();
#pragma unroll
    for (int i = 0; i < 16; ++i) red[tid * 16 + i] = ssum[i];
    __syncthreads();
    if (tid < 128) {
        int o = tid >> 4, i = tid & 15;
        float s = 0.f;
        for (int ss = 0; ss < 32; ++ss) s += red[(ss * 8 + o) * 16 + i];
        g_psum[g * 128 + o * 16 + i] = s;
    }
    __syncthreads();
#pragma unroll
    for (int i = 0; i < 16; ++i) red[tid * 16 + i] = ssq[i];
    __syncthreads();
    if (tid < 128) {
        int o = tid >> 4, i = tid & 15;
        float s = 0.f;
        for (int ss = 0; ss < 32; ++ss) s += red[(ss * 8 + o) * 16 + i];
        g_psq[g * 128 + o * 16 + i] = s;
    }
}

// ---------------- K5: BN stats -> scale/shift ----------------
__global__ void k_stats(const float* __restrict__ bn_g, const float* __restrict__ bn_b, int N) {
    int t = threadIdx.x;  // 128
    float s = 0.f, q = 0.f;
    for (int g = 0; g < NG; ++g) {
        s += g_psum[g * 128 + t];
        q += g_psq[g * 128 + t];
    }
    float invN = 1.f / (float)N;
    float mu  = s * invN;
    float var = fmaxf(q * invN - mu * mu, 0.f);
    float sc  = rsqrtf(var + BN_EPS) * bn_g[t];
    g_scale[t] = sc;
    g_shift[t] = bn_b[t] - mu * sc;
}

// ---------------- K6: out = x + y0*scale + shift ----------------
__global__ void k_out(const float* __restrict__ x, float* __restrict__ out, int total4) {
    int i = blockIdx.x * blockDim.x + threadIdx.x;
    if (i >= total4) return;
    int j4 = i & 31;
    float4 sc = ((const float4*)g_scale)[j4];
    float4 sh = ((const float4*)g_shift)[j4];
    float4 xv = ((const float4*)x)[i];
    float4 yv = ((const float4*)g_y)[i];
    float4 o;
    o.x = xv.x + yv.x * sc.x + sh.x;
    o.y = xv.y + yv.y * sc.y + sh.y;
    o.z = xv.z + yv.z * sc.z + sh.z;
    o.w = xv.w + yv.w * sc.w + sh.w;
    ((float4*)out)[i] = o;
}

// ---------------- launch ----------------
extern "C" void kernel_launch(void* const* d_in, const int* in_sizes, int n_in,
                              void* d_out, int out_size) {
    const float* x     = (const float*)d_in[0];
    const int*   batch = (const int*)d_in[1];
    const float* pers0 = (const float*)d_in[2];
    const float* g1w   = (const float*)d_in[3];
    const float* g1b   = (const float*)d_in[4];
    const float* l1w   = (const float*)d_in[5];
    const float* g2w   = (const float*)d_in[6];
    const float* g2b   = (const float*)d_in[7];
    const float* l2w   = (const float*)d_in[8];
    const float* bng   = (const float*)d_in[9];
    const float* bnb   = (const float*)d_in[10];
    float* out = (float*)d_out;
    int N = in_sizes[0] / 128;

    cudaFuncSetAttribute(k_gemm1, cudaFuncAttributeMaxDynamicSharedMemorySize, SMEM_G1);
    cudaFuncSetAttribute(k_gemm2, cudaFuncAttributeMaxDynamicSharedMemorySize, SMEM_G2);

    k_bounds<<<(NG + 256) / 256, 256>>>(batch, N);
    k_lam1<<<NG, 288>>>(x, pers0, l1w, N);
    k_gemm1<<<NG, 256, SMEM_G1>>>(x, pers0, g1w, g1b, l2w, N);
    k_gemm2<<<NG, 256, SMEM_G2>>>(g2w, g2b, N);
    k_stats<<<1, 128>>>(bng, bnb, N);
    int total4 = N * 32;
    k_out<<<(total4 + 255) / 256, 256>>>(x, out, total4);
}

// round 11
// speedup vs baseline: 1.0414x; 1.0414x over previous
#include <cuda_runtime.h>
#include <cuda_bf16.h>
#include <cstdint>

#define NG   2048
#define MAXN 500000
#define BN_EPS 1e-5f

typedef unsigned long long ull;

// ---------------- scratch (device globals; no allocation allowed) ----------------
__device__ __align__(16) __nv_bfloat16 g_hhi[(size_t)MAXN * 128];
__device__ __align__(16) __nv_bfloat16 g_hlo[(size_t)MAXN * 128];
__device__ __align__(16) float g_y[(size_t)MAXN * 128];
__device__ __align__(16) float g_lam1[NG * 128];
__device__ __align__(16) float g_lam2[NG * 128];
__device__ __align__(16) float g_psum[NG * 128];
__device__ __align__(16) float g_psq[NG * 128];
__device__ __align__(16) float g_scale[128];
__device__ __align__(16) float g_shift[128];
__device__ int g_seg[NG + 1];

// ---------------- helpers ----------------
__device__ __forceinline__ uint32_t smaddr(const void* p) {
    return (uint32_t)__cvta_generic_to_shared(p);
}
__device__ __forceinline__ void cp16(uint32_t d, const void* s, int n) {
    asm volatile("cp.async.ca.shared.global [%0], [%1], 16, %2;\n" :: "r"(d), "l"(s), "r"(n));
}
#define CP_COMMIT() asm volatile("cp.async.commit_group;\n" ::: "memory")
#define CP_WAIT0()  asm volatile("cp.async.wait_group 0;\n" ::: "memory")

__device__ __forceinline__ void mma_bf16(float* d, const uint32_t* a, const uint32_t* b) {
    asm volatile(
        "mma.sync.aligned.m16n8k16.row.col.f32.bf16.bf16.f32 "
        "{%0,%1,%2,%3}, {%4,%5,%6,%7}, {%8,%9}, {%0,%1,%2,%3};"
        : "+f"(d[0]), "+f"(d[1]), "+f"(d[2]), "+f"(d[3])
        : "r"(a[0]), "r"(a[1]), "r"(a[2]), "r"(a[3]), "r"(b[0]), "r"(b[1]));
}
__device__ __forceinline__ void ldsm4(uint32_t* r, uint32_t a) {
    asm volatile("ldmatrix.sync.aligned.m8n8.x4.shared.b16 {%0,%1,%2,%3}, [%4];"
        : "=r"(r[0]), "=r"(r[1]), "=r"(r[2]), "=r"(r[3]) : "r"(a));
}

__device__ __forceinline__ void bsplit2(float a, float b, uint32_t& hi, uint32_t& lo) {
    __nv_bfloat162 h = __floats2bfloat162_rn(a, b);
    hi = *reinterpret_cast<uint32_t*>(&h);
    float ra = a - __bfloat162float(h.x);
    float rb = b - __bfloat162float(h.y);
    __nv_bfloat162 l = __floats2bfloat162_rn(ra, rb);
    lo = *reinterpret_cast<uint32_t*>(&l);
}

// ---- gemm1 smem map (64-row tiles, ROWB=304, K=144) ----
#define ROWB 304
#define OFF_BH 512
#define OFF_BL (OFF_BH + 38912)
#define OFF_A  (OFF_BL + 38912)        // 78336; 2 bufs x 38912 (hi 19456 + lo 19456)
#define OFF_EPI (OFF_A + 77824)        // 156160
#define SMEM_G1 (OFF_EPI + 33792)      // 189952 B

// ---- gemm2 smem map (64-row tiles, ROWB2=272, K=128) ----
#define ROWB2 272
#define O2_BH 512
#define O2_BL (O2_BH + 34816)
#define O2_A  (O2_BL + 34816)          // 70144; 2 bufs x 34816 (hi 17408 + lo 17408)
#define O2_EPI (O2_A + 69632)          // 139776
#define SMEM_G2 (O2_EPI + 33792)       // 173568 B

// ---------------- K0: segment bounds (batch sorted) ----------------
__global__ void k_bounds(const int* __restrict__ batch, int N) {
    int g = blockIdx.x * blockDim.x + threadIdx.x;
    if (g > NG) return;
    int lo = 0, hi = N;
    while (lo < hi) {
        int mid = (lo + hi) >> 1;
        if (batch[mid] < g) lo = mid + 1; else hi = mid;
    }
    g_seg[g] = lo;
}

// ---------------- K1: per-graph col means of x0 + lam1 = xm @ l1w^T ----------------
__global__ void k_lam1(const float* __restrict__ x, const float* __restrict__ pers0,
                       const float* __restrict__ l1w, int N) {
    __shared__ float s_sum[2][144];
    __shared__ float s_xm[144];
    int g  = blockIdx.x;
    int lo = g_seg[g], hi = g_seg[g + 1];
    int t  = threadIdx.x;
    int phase = t / 144, col = t - phase * 144;

    float acc = 0.f;
    if (col < 128) {
        const float* p = x + col;
        for (int r = lo + phase; r < hi; r += 2) acc += p[(size_t)r * 128];
    } else {
        int j = col - 128;
        int pp = j >> 1, c = j & 1;
        const float* p = pers0 + (size_t)pp * 2 * N + c;
        for (int r = lo + phase; r < hi; r += 2) acc += p[2 * (size_t)r];
    }
    s_sum[phase][col] = acc;
    __syncthreads();
    if (t < 144) {
        float cnt = (float)max(hi - lo, 1);
        s_xm[t] = (s_sum[0][t] + s_sum[1][t]) / cnt;
    }
    __syncthreads();
    if (t < 128) {
        const float* w = l1w + t * 144;
        float a = 0.f;
#pragma unroll 8
        for (int k = 0; k < 144; ++k) a += s_xm[k] * w[k];
        g_lam1[g * 128 + t] = a;
    }
}

// =============== K2: mma.sync GEMM1 (512 thr): h = relu(x0 @ g1w^T + g1b - lam1[g]) ===============
// 64-row tiles, 16 warps as 2M x 8N (warp: 32 rows x 16 cols). K=144 = 9 k16 steps.
__global__ __launch_bounds__(512, 1) void k_gemm1(
    const float* __restrict__ x, const float* __restrict__ pers0,
    const float* __restrict__ g1w, const float* __restrict__ g1b,
    const float* __restrict__ l2w, int N) {
    extern __shared__ char sm[];
    uint32_t su = smaddr(sm);
    float* sbias = (float*)sm;
    int g  = blockIdx.x;
    int lo = g_seg[g], hi = g_seg[g + 1];
    int tid = threadIdx.x;
    int wid = tid >> 5, l = tid & 31;
    int wm = wid & 1, wn = wid >> 1;           // 2M x 8N
    int seg = l >> 3, l7 = l & 7, gg = l >> 2, tg = l & 3;

    // stage B = g1w as bf16 hi/lo, row stride 304B
    for (int it = 0; it < 9; ++it) {
        int idx = tid + it * 512;            // [0, 128*36)
        int jr = idx / 36, k4 = idx - jr * 36;
        float4 v = ((const float4*)g1w)[idx];
        uint32_t h01, l01, h23, l23;
        bsplit2(v.x, v.y, h01, l01);
        bsplit2(v.z, v.w, h23, l23);
        int off = jr * ROWB + k4 * 8;
        *(uint2*)(sm + OFF_BH + off) = make_uint2(h01, h23);
        *(uint2*)(sm + OFF_BL + off) = make_uint2(l01, l23);
    }
    if (tid < 128) sbias[tid] = g1b[tid] - g_lam1[g * 128 + tid];

    // register prefetch of one 64-row x0 tile (row = tid>>3, k-eighth = tid&7)
    float4 xv[4]; float2 pv;
    int prow = tid >> 3, pk8 = tid & 7;
    auto loadRegs = [&](int r0i, int rem) {
        int rg = r0i + min(prow, rem - 1);
        const float4* xs = (const float4*)(x + (size_t)rg * 128) + pk8 * 4;
#pragma unroll
        for (int i = 0; i < 4; ++i) xv[i] = xs[i];
        pv = ((const float2*)pers0)[(size_t)pk8 * N + rg];
    };
    auto stsRegs = [&](int buf) {
        char* bh = sm + OFF_A + buf * 38912 + prow * ROWB;
        char* bl = bh + 19456;
#pragma unroll
        for (int i = 0; i < 4; ++i) {
            uint32_t h01, l01, h23, l23;
            bsplit2(xv[i].x, xv[i].y, h01, l01);
            bsplit2(xv[i].z, xv[i].w, h23, l23);
            *(uint2*)(bh + pk8 * 32 + i * 8) = make_uint2(h01, h23);
            *(uint2*)(bl + pk8 * 32 + i * 8) = make_uint2(l01, l23);
        }
        uint32_t h, lw;
        bsplit2(pv.x, pv.y, h, lw);
        *(uint32_t*)(bh + 256 + 4 * pk8) = h;
        *(uint32_t*)(bl + 256 + 4 * pk8) = lw;
    };

    float hs[16];
#pragma unroll
    for (int i = 0; i < 16; ++i) hs[i] = 0.f;

    uint32_t a_off = su + OFF_A  + (uint32_t)((wm * 32 + (seg & 1) * 8 + l7) * ROWB + (seg >> 1) * 16);
    uint32_t b_off = su + OFF_BH + (uint32_t)((wn * 16 + (seg >> 1) * 8 + l7) * ROWB + (seg & 1) * 16);

    if (lo < hi) { loadRegs(lo, min(64, hi - lo)); stsRegs(0); }
    __syncthreads();

    int t = 0;
    for (int r0 = lo; r0 < hi; r0 += 64, ++t) {
        int buf = t & 1;
        int nr0 = r0 + 64;
        bool havnext = nr0 < hi;
        if (havnext) loadRegs(nr0, min(64, hi - nr0));

        float D[4][4];
#pragma unroll
        for (int i = 0; i < 4; ++i)
#pragma unroll
            for (int q = 0; q < 4; ++q) D[i][q] = 0.f;

        uint32_t abase = a_off + buf * 38912;
#pragma unroll
        for (int ks = 0; ks < 9; ++ks) {
            uint32_t ah[2][4], al[2][4], bh4[4], bl4[4];
            ldsm4(ah[0], abase + ks * 32);
            ldsm4(al[0], abase + 19456 + ks * 32);
            ldsm4(ah[1], abase + 16 * ROWB + ks * 32);
            ldsm4(al[1], abase + 16 * ROWB + 19456 + ks * 32);
            ldsm4(bh4, b_off + ks * 32);
            ldsm4(bl4, b_off + 38912 + ks * 32);
#pragma unroll
            for (int m = 0; m < 2; ++m) {
                float* d0 = D[m * 2];
                float* d1 = D[m * 2 + 1];
                mma_bf16(d0, ah[m], bh4);
                mma_bf16(d1, ah[m], bh4 + 2);
                mma_bf16(d0, ah[m], bl4);
                mma_bf16(d1, ah[m], bl4 + 2);
                mma_bf16(d0, al[m], bh4);
                mma_bf16(d1, al[m], bh4 + 2);
            }
        }
        if (havnext) stsRegs(buf ^ 1);

        // single-phase epilogue: all 64 rows
        float* epi = (float*)(sm + OFF_EPI);
#pragma unroll
        for (int m = 0; m < 2; ++m)
#pragma unroll
        for (int h = 0; h < 2; ++h) {
            int d = m * 2 + h;
            int er = wm * 32 + m * 16 + gg;
            int c = wn * 16 + h * 8 + 2 * tg;
            *(float2*)(epi + er * 132 + c)       = make_float2(D[d][0], D[d][1]);
            *(float2*)(epi + (er + 8) * 132 + c) = make_float2(D[d][2], D[d][3]);
        }
        __syncthreads();
        {
            int r = tid >> 3, c0 = (tid & 7) * 16;
            int grow = r0 + r;
            if (grow < hi) {
                float v[16];
#pragma unroll
                for (int q = 0; q < 4; ++q)
                    *(float4*)(v + 4 * q) = *(const float4*)(epi + r * 132 + c0 + 4 * q);
                uint32_t hh[8], ll[8];
#pragma unroll
                for (int i = 0; i < 16; i += 2) {
                    float va = fmaxf(v[i]     + sbias[c0 + i],     0.f);
                    float vb = fmaxf(v[i + 1] + sbias[c0 + i + 1], 0.f);
                    hs[i] += va; hs[i + 1] += vb;
                    bsplit2(va, vb, hh[i >> 1], ll[i >> 1]);
                }
                size_t off = (size_t)grow * 128 + c0;
                *(uint4*)(g_hhi + off)     = make_uint4(hh[0], hh[1], hh[2], hh[3]);
                *(uint4*)(g_hhi + off + 8) = make_uint4(hh[4], hh[5], hh[6], hh[7]);
                *(uint4*)(g_hlo + off)     = make_uint4(ll[0], ll[1], ll[2], ll[3]);
                *(uint4*)(g_hlo + off + 8) = make_uint4(ll[4], ll[5], ll[6], ll[7]);
            }
        }
        __syncthreads();
    }

    // deterministic col-sum reduce -> hm -> lam2 = hm @ l2w^T
    float* red = (float*)(sm + OFF_EPI);
    __syncthreads();
#pragma unroll
    for (int i = 0; i < 16; ++i) red[tid * 16 + i] = hs[i];
    __syncthreads();
    if (tid < 128) {
        int o = tid >> 4, i = tid & 15;
        float s = 0.f;
        for (int ss = 0; ss < 64; ++ss) s += red[(ss * 8 + o) * 16 + i];
        float cnt = (float)max(hi - lo, 1);
        red[8192 + o * 16 + i] = s / cnt;
    }
    __syncthreads();
    if (tid < 128) {
        const float* w = l2w + tid * 128;
        const float* hm = red + 8192;
        float a = 0.f;
#pragma unroll 8
        for (int k = 0; k < 128; ++k) a += hm[k] * w[k];
        g_lam2[g * 128 + tid] = a;
    }
}

// =============== K4: mma.sync GEMM2 (512 thr): y0 = h @ g2w^T + g2b - lam2[g]; BN partials ===============
// 64-row tiles, 16 warps as 2M x 8N (warp: 32 rows x 16 cols). K=128 = 8 k16 steps.
__global__ __launch_bounds__(512, 1) void k_gemm2(
    const float* __restrict__ g2w, const float* __restrict__ g2b, int N) {
    extern __shared__ char sm[];
    uint32_t su = smaddr(sm);
    float* sbias = (float*)sm;
    int g  = blockIdx.x;
    int lo = g_seg[g], hi = g_seg[g + 1];
    int tid = threadIdx.x;
    int wid = tid >> 5, l = tid & 31;
    int wm = wid & 1, wn = wid >> 1;
    int seg = l >> 3, l7 = l & 7, gg = l >> 2, tg = l & 3;

    // stage B = g2w bf16 hi/lo (K=128), row stride 272B
    for (int it = 0; it < 8; ++it) {
        int idx = tid + it * 512;            // [0, 128*32)
        int jr = idx >> 5, k4 = idx & 31;
        float4 v = ((const float4*)g2w)[idx];
        uint32_t h01, l01, h23, l23;
        bsplit2(v.x, v.y, h01, l01);
        bsplit2(v.z, v.w, h23, l23);
        int off = jr * ROWB2 + k4 * 8;
        *(uint2*)(sm + O2_BH + off) = make_uint2(h01, h23);
        *(uint2*)(sm + O2_BL + off) = make_uint2(l01, l23);
    }
    if (tid < 128) sbias[tid] = g2b[tid] - g_lam2[g * 128 + tid];

    // A staging via cp.async from pre-split h arrays (64 rows per tile)
    auto stageA = [&](int r0i, int rem, int buf) {
#pragma unroll
        for (int hl = 0; hl < 2; ++hl) {
            const __nv_bfloat16* src = hl ? g_hlo : g_hhi;
            uint32_t base = su + O2_A + buf * 34816 + hl * 17408;
#pragma unroll
            for (int it = 0; it < 2; ++it) {
                int idx = tid + it * 512;        // [0, 64*16)
                int r = idx >> 4, u = idx & 15;
                int rc = (r < rem) ? r : 0;
                cp16(base + r * ROWB2 + u * 16,
                     src + (size_t)(r0i + rc) * 128 + u * 8, (r < rem) ? 16 : 0);
            }
        }
    };

    float ssum[16], ssq[16];
#pragma unroll
    for (int i = 0; i < 16; ++i) { ssum[i] = 0.f; ssq[i] = 0.f; }

    uint32_t a_off = su + O2_A  + (uint32_t)((wm * 32 + (seg & 1) * 8 + l7) * ROWB2 + (seg >> 1) * 16);
    uint32_t b_off = su + O2_BH + (uint32_t)((wn * 16 + (seg >> 1) * 8 + l7) * ROWB2 + (seg & 1) * 16);

    if (lo < hi) { stageA(lo, min(64, hi - lo), 0); CP_COMMIT(); CP_WAIT0(); }
    __syncthreads();

    int t = 0;
    for (int r0 = lo; r0 < hi; r0 += 64, ++t) {
        int buf = t & 1;
        int nr0 = r0 + 64;
        bool havnext = nr0 < hi;
        if (havnext) { stageA(nr0, min(64, hi - nr0), buf ^ 1); CP_COMMIT(); }

        float D[4][4];
#pragma unroll
        for (int i = 0; i < 4; ++i)
#pragma unroll
            for (int q = 0; q < 4; ++q) D[i][q] = 0.f;

        // A bufs: hi at +0, lo at +17408 within 34816-byte buffer
        uint32_t abase = a_off + buf * 34816;
#pragma unroll
        for (int ks = 0; ks < 8; ++ks) {
            uint32_t ah[2][4], al[2][4], bh4[4], bl4[4];
            ldsm4(ah[0], abase + ks * 32);
            ldsm4(al[0], abase + 17408 + ks * 32);
            ldsm4(ah[1], abase + 16 * ROWB2 + ks * 32);
            ldsm4(al[1], abase + 16 * ROWB2 + 17408 + ks * 32);
            ldsm4(bh4, b_off + ks * 32);
            ldsm4(bl4, b_off + 34816 + ks * 32);
#pragma unroll
            for (int m = 0; m < 2; ++m) {
                float* d0 = D[m * 2];
                float* d1 = D[m * 2 + 1];
                mma_bf16(d0, ah[m], bh4);
                mma_bf16(d1, ah[m], bh4 + 2);
                mma_bf16(d0, ah[m], bl4);
                mma_bf16(d1, ah[m], bl4 + 2);
                mma_bf16(d0, al[m], bh4);
                mma_bf16(d1, al[m], bh4 + 2);
            }
        }

        // single-phase epilogue: all 64 rows
        float* epi = (float*)(sm + O2_EPI);
#pragma unroll
        for (int m = 0; m < 2; ++m)
#pragma unroll
        for (int h = 0; h < 2; ++h) {
            int d = m * 2 + h;
            int er = wm * 32 + m * 16 + gg;
            int c = wn * 16 + h * 8 + 2 * tg;
            *(float2*)(epi + er * 132 + c)       = make_float2(D[d][0], D[d][1]);
            *(float2*)(epi + (er + 8) * 132 + c) = make_float2(D[d][2], D[d][3]);
        }
        __syncthreads();
        {
            int r = tid >> 3, c0 = (tid & 7) * 16;
            int grow = r0 + r;
            if (grow < hi) {
                float v[16];
#pragma unroll
                for (int q = 0; q < 4; ++q)
                    *(float4*)(v + 4 * q) = *(const float4*)(epi + r * 132 + c0 + 4 * q);
#pragma unroll
                for (int i = 0; i < 16; ++i) {
                    float vv = v[i] + sbias[c0 + i];
                    v[i] = vv;
                    ssum[i] += vv;
                    ssq[i]  += vv * vv;
                }
                float* dst = g_y + (size_t)grow * 128 + c0;
#pragma unroll
                for (int q = 0; q < 4; ++q) *(float4*)(dst + 4 * q) = *(float4*)(v + 4 * q);
            }
        }
        if (havnext) CP_WAIT0();
        __syncthreads();
    }

    // deterministic BN partials
    float* red = (float*)(sm + O2_EPI);
    __syncthreads();
#pragma unroll
    for (int i = 0; i < 16; ++i) red[tid * 16 + i] = ssum[i];
    __syncthreads();
    if (tid < 128) {
        int o = tid >> 4, i = tid & 15;
        float s = 0.f;
        for (int ss = 0; ss < 64; ++ss) s += red[(ss * 8 + o) * 16 + i];
        g_psum[g * 128 + o * 16 + i] = s;
    }
    __syncthreads();
#pragma unroll
    for (int i = 0; i < 16; ++i) red[tid * 16 + i] = ssq[i];
    __syncthreads();
    if (tid < 128) {
        int o = tid >> 4, i = tid & 15;
        float s = 0.f;
        for (int ss = 0; ss < 64; ++ss) s += red[(ss * 8 + o) * 16 + i];
        g_psq[g * 128 + o * 16 + i] = s;
    }
}

// ---------------- K5: BN stats -> scale/shift ----------------
__global__ void k_stats(const float* __restrict__ bn_g, const float* __restrict__ bn_b, int N) {
    int t = threadIdx.x;  // 128
    float s = 0.f, q = 0.f;
    for (int g = 0; g < NG; ++g) {
        s += g_psum[g * 128 + t];
        q += g_psq[g * 128 + t];
    }
    float invN = 1.f / (float)N;
    float mu  = s * invN;
    float var = fmaxf(q * invN - mu * mu, 0.f);
    float sc  = rsqrtf(var + BN_EPS) * bn_g[t];
    g_scale[t] = sc;
    g_shift[t] = bn_b[t] - mu * sc;
}

// ---------------- K6: out = x + y0*scale + shift ----------------
__global__ void k_out(const float* __restrict__ x, float* __restrict__ out, int total4) {
    int i = blockIdx.x * blockDim.x + threadIdx.x;
    if (i >= total4) return;
    int j4 = i & 31;
    float4 sc = ((const float4*)g_scale)[j4];
    float4 sh = ((const float4*)g_shift)[j4];
    float4 xv = ((const float4*)x)[i];
    float4 yv = ((const float4*)g_y)[i];
    float4 o;
    o.x = xv.x + yv.x * sc.x + sh.x;
    o.y = xv.y + yv.y * sc.y + sh.y;
    o.z = xv.z + yv.z * sc.z + sh.z;
    o.w = xv.w + yv.w * sc.w + sh.w;
    ((float4*)out)[i] = o;
}

// ---------------- launch ----------------
extern "C" void kernel_launch(void* const* d_in, const int* in_sizes, int n_in,
                              void* d_out, int out_size) {
    const float* x     = (const float*)d_in[0];
    const int*   batch = (const int*)d_in[1];
    const float* pers0 = (const float*)d_in[2];
    const float* g1w   = (const float*)d_in[3];
    const float* g1b   = (const float*)d_in[4];
    const float* l1w   = (const float*)d_in[5];
    const float* g2w   = (const float*)d_in[6];
    const float* g2b   = (const float*)d_in[7];
    const float* l2w   = (const float*)d_in[8];
    const float* bng   = (const float*)d_in[9];
    const float* bnb   = (const float*)d_in[10];
    float* out = (float*)d_out;
    int N = in_sizes[0] / 128;

    cudaFuncSetAttribute(k_gemm1, cudaFuncAttributeMaxDynamicSharedMemorySize, SMEM_G1);
    cudaFuncSetAttribute(k_gemm2, cudaFuncAttributeMaxDynamicSharedMemorySize, SMEM_G2);

    k_bounds<<<(NG + 256) / 256, 256>>>(batch, N);
    k_lam1<<<NG, 288>>>(x, pers0, l1w, N);
    k_gemm1<<<NG, 512, SMEM_G1>>>(x, pers0, g1w, g1b, l2w, N);
    k_gemm2<<<NG, 512, SMEM_G2>>>(g2w, g2b, N);
    k_stats<<<1, 128>>>(bng, bnb, N);
    int total4 = N * 32;
    k_out<<<(total4 + 255) / 256, 256>>>(x, out, total4);
}